// round 11
// baseline (speedup 1.0000x reference)
#include <cuda_runtime.h>
#include <cuda_bf16.h>
#include <cstdint>

#define HID 256
#define FEA 192
#define NMAX 50000
#define EMAX 800000
#define MB 64           // nodes per block
#define NT 256          // threads per block

typedef unsigned long long ull;

// node kernel smem layout (bytes)
#define AST     264                        // act row stride in halfs
#define SM_AH   0
#define SM_AL   (MB * AST * 2)             // 33792
#define SM_W    (2 * MB * AST * 2)         // 67584 (weight bufs / edge staging)
#define CHUNK_B 9216
#define SM_BIAS (SM_W + 4 * CHUNK_B)       // 104448
#define SM_RED  (SM_BIAS + 5 * FEA * 4)    // 108288
#define SM_TOT  (SM_RED + 2 * MB * 4)      // 108800 -> 2 CTAs/SM

__device__ int g_idx_is64;
// CSR sort structures
__device__ int g_cnt[NMAX];
__device__ int g_off[NMAX + 1];
__device__ int g_cur[NMAX];
__device__ int g_sorted[EMAX];
__device__ int g_nid[EMAX];
__device__ float g_rbf_s[(size_t)EMAX * 6];   // rbf rows in sorted-edge order
// pre-split weights, chunked layout: [chunk16][n(192)][kk(16)]
#define W_ELEMS (HID * FEA + 3 * FEA * FEA)
__device__ __align__(16) __nv_bfloat16 g_wh[W_ELEMS];
__device__ __align__(16) __nv_bfloat16 g_wl[W_ELEMS];
#define L0_OFF 0
#define L_OFF(l) (HID * FEA + ((l) - 1) * FEA * FEA)

// ---------------------------------------------------------------------------
// helpers
// ---------------------------------------------------------------------------
__device__ __forceinline__ void split1(float v, uint16_t& h, uint16_t& l) {
    __nv_bfloat16 hb = __float2bfloat16(v);
    float r = v - __bfloat162float(hb);
    __nv_bfloat16 lb = __float2bfloat16(r);
    h = __bfloat16_as_ushort(hb);
    l = __bfloat16_as_ushort(lb);
}
__device__ __forceinline__ void split2(float a, float b, uint32_t& hw, uint32_t& lw) {
    uint16_t ha, la, hb, lb;
    split1(a, ha, la);
    split1(b, hb, lb);
    hw = ((uint32_t)hb << 16) | ha;
    lw = ((uint32_t)lb << 16) | la;
}
__device__ __forceinline__ void mma_bf16(float* d,
                                         uint32_t a0, uint32_t a1, uint32_t a2, uint32_t a3,
                                         uint32_t b0, uint32_t b1) {
    asm volatile(
        "mma.sync.aligned.m16n8k16.row.col.f32.bf16.bf16.f32 "
        "{%0,%1,%2,%3}, {%4,%5,%6,%7}, {%8,%9}, {%0,%1,%2,%3};"
        : "+f"(d[0]), "+f"(d[1]), "+f"(d[2]), "+f"(d[3])
        : "r"(a0), "r"(a1), "r"(a2), "r"(a3), "r"(b0), "r"(b1));
}
__device__ __forceinline__ uint32_t smem_to_u32(const void* p) {
    uint32_t a;
    asm("{ .reg .u64 t; cvta.to.shared.u64 t, %1; cvt.u32.u64 %0, t; }"
        : "=r"(a) : "l"(p));
    return a;
}
__device__ __forceinline__ int load_idx(const void* idx, int e, int is64) {
    return is64 ? (int)reinterpret_cast<const long long*>(idx)[e]
                : reinterpret_cast<const int*>(idx)[e];
}

// ---------------------------------------------------------------------------
// prep: split all weights to bf16 hi/lo, chunked layout
// ---------------------------------------------------------------------------
__global__ void prep_kernel(const float* __restrict__ W_up,
                            const float* __restrict__ W_lins) {
    int t = blockIdx.x * blockDim.x + threadIdx.x;
    if (t >= W_ELEMS) return;
    int base, el;
    const float* src;
    if (t < HID * FEA) { base = L0_OFF; el = t; src = W_up; }
    else {
        int t2 = t - HID * FEA;
        int l = t2 / (FEA * FEA);
        base = L_OFF(l + 1);
        el = t2 - l * FEA * FEA;
        src = W_lins + l * FEA * FEA;
    }
    int kf = el / FEA, n = el - kf * FEA;
    uint16_t h, l16;
    split1(src[kf * FEA + n], h, l16);
    int dst = base + (kf >> 4) * (16 * FEA) + n * 16 + (kf & 15);
    g_wh[dst] = __ushort_as_bfloat16(h);
    g_wl[dst] = __ushort_as_bfloat16(l16);
}

// ---------------------------------------------------------------------------
// sort chain
// ---------------------------------------------------------------------------
__global__ void detect_idx_kernel(const unsigned int* __restrict__ w, int E) {
    __shared__ int bad;
    if (threadIdx.x == 0) bad = 0;
    __syncthreads();
    int n = E < 512 ? E : 512;
    for (int k = threadIdx.x; k < n; k += blockDim.x)
        if (w[2 * k + 1] != 0u) bad = 1;
    __syncthreads();
    if (threadIdx.x == 0) g_idx_is64 = !bad;
}

__global__ void zero_cnt_kernel(int N) {
    int t = blockIdx.x * blockDim.x + threadIdx.x;
    if (t < N) g_cnt[t] = 0;
}

__global__ void hist_kernel(const void* __restrict__ idx, int E) {
    int e = blockIdx.x * blockDim.x + threadIdx.x;
    if (e >= E) return;
    atomicAdd(&g_cnt[load_idx(idx, e, g_idx_is64)], 1);
}

__global__ __launch_bounds__(1024) void scan_kernel(int N) {
    __shared__ int part[1024];
    const int tid = threadIdx.x;
    const int chunk = (N + 1023) / 1024;
    const int base = tid * chunk;
    int s = 0;
    for (int k = 0; k < chunk; k++) {
        int i = base + k;
        if (i < N) s += g_cnt[i];
    }
    part[tid] = s;
    __syncthreads();
    for (int d = 1; d < 1024; d <<= 1) {
        int v = (tid >= d) ? part[tid - d] : 0;
        __syncthreads();
        part[tid] += v;
        __syncthreads();
    }
    int run = part[tid] - s;
    for (int k = 0; k < chunk; k++) {
        int i = base + k;
        if (i < N) {
            g_off[i] = run;
            g_cur[i] = run;
            run += g_cnt[i];
        }
    }
    if (tid == 1023) g_off[N] = part[1023];
}

__global__ void scatter_kernel(const void* __restrict__ idx, int E) {
    int e = blockIdx.x * blockDim.x + threadIdx.x;
    if (e >= E) return;
    int n = load_idx(idx, e, g_idx_is64);
    int p = atomicAdd(&g_cur[n], 1);
    g_sorted[p] = e;
    g_nid[p] = n;
}

// gather rbf rows into sorted-edge order (coalesced writes, L2-served reads)
__global__ void rbf_sort_kernel(const float* __restrict__ rbf, int E) {
    int p = blockIdx.x * blockDim.x + threadIdx.x;
    if (p >= E) return;
    int e = g_sorted[p];
    const float2* s = reinterpret_cast<const float2*>(rbf + (size_t)e * 6);
    float2* d = reinterpret_cast<float2*>(g_rbf_s + (size_t)p * 6);
    float2 v0 = s[0], v1 = s[1], v2 = s[2];
    d[0] = v0; d[1] = v1; d[2] = v2;
}

// ---------------------------------------------------------------------------
// node MLP machinery (mma.sync bf16 3-term split)
// ---------------------------------------------------------------------------
__device__ __forceinline__ void stage_chunk(
    const __nv_bfloat16* __restrict__ Wh, const __nv_bfloat16* __restrict__ Wl,
    int s, int buf, uint32_t smem_u32, int tid)
{
    const char* srcH = reinterpret_cast<const char*>(Wh + s * 16 * FEA);
    const char* srcL = reinterpret_cast<const char*>(Wl + s * 16 * FEA);
#pragma unroll
    for (int it = 0; it < 3; it++) {
        int t = tid + it * NT;
        int term = t >= 384;
        int u = term ? t - 384 : t;
        int n = u >> 1, seg = u & 1;
        const char* src = (term ? srcL : srcH) + n * 32 + seg * 16;
        uint32_t dst = smem_u32 + SM_W + term * (2 * CHUNK_B) + buf * CHUNK_B
                     + n * 48 + seg * 16;
        asm volatile("cp.async.cg.shared.global [%0], [%1], 16;"
                     :: "r"(dst), "l"(src));
    }
    asm volatile("cp.async.commit_group;");
}

template<int K>
__device__ __forceinline__ void mloop(
    const __nv_bfloat16* __restrict__ Wh, const __nv_bfloat16* __restrict__ Wl,
    float (&d)[12][4], char* smem, uint32_t smem_u32,
    int tid, int g, int q, int warp_m, int warp_n)
{
#pragma unroll
    for (int j = 0; j < 12; j++)
#pragma unroll
        for (int u = 0; u < 4; u++) d[j][u] = 0.f;

    stage_chunk(Wh, Wl, 0, 0, smem_u32, tid);

    const uint32_t* Ahw = reinterpret_cast<const uint32_t*>(smem + SM_AH);
    const uint32_t* Alw = reinterpret_cast<const uint32_t*>(smem + SM_AL);
    const int r0 = warp_m * 16 + g;
    constexpr int S = K / 16;

#pragma unroll 2
    for (int s = 0; s < S; s++) {
        const int b = s & 1;
        if (s + 1 < S) {
            stage_chunk(Wh, Wl, s + 1, b ^ 1, smem_u32, tid);
            asm volatile("cp.async.wait_group 1;");
        } else {
            asm volatile("cp.async.wait_group 0;");
        }
        __syncthreads();

        const int base = r0 * (AST / 2) + s * 8 + q;
        uint32_t ah[4], al[4];
        ah[0] = Ahw[base];
        ah[1] = Ahw[base + 8 * (AST / 2)];
        ah[2] = Ahw[base + 4];
        ah[3] = Ahw[base + 8 * (AST / 2) + 4];
        al[0] = Alw[base];
        al[1] = Alw[base + 8 * (AST / 2)];
        al[2] = Alw[base + 4];
        al[3] = Alw[base + 8 * (AST / 2) + 4];

        const uint32_t* bhp = reinterpret_cast<const uint32_t*>(smem + SM_W + b * CHUNK_B);
        const uint32_t* blp = reinterpret_cast<const uint32_t*>(smem + SM_W + 2 * CHUNK_B + b * CHUNK_B);
#pragma unroll
        for (int j = 0; j < 12; j++) {
            int n = warp_n * 96 + j * 8 + g;
            uint32_t bh0 = bhp[n * 12 + q], bh1 = bhp[n * 12 + 4 + q];
            uint32_t bl0 = blp[n * 12 + q], bl1 = blp[n * 12 + 4 + q];
            mma_bf16(d[j], ah[0], ah[1], ah[2], ah[3], bh0, bh1);
            mma_bf16(d[j], al[0], al[1], al[2], al[3], bh0, bh1);
            mma_bf16(d[j], ah[0], ah[1], ah[2], ah[3], bl0, bl1);
        }
        __syncthreads();
    }
}

template<bool ACT>
__device__ __forceinline__ void epi_store(
    float (&d)[12][4], const float* __restrict__ bias,
    char* smem, int g, int q, int warp_m, int warp_n)
{
    uint32_t* Ahw = reinterpret_cast<uint32_t*>(smem + SM_AH);
    uint32_t* Alw = reinterpret_cast<uint32_t*>(smem + SM_AL);
    const int r0 = warp_m * 16 + g;
#pragma unroll
    for (int j = 0; j < 12; j++) {
        int c = warp_n * 96 + j * 8 + q * 2;
        float b0 = bias[c], b1 = bias[c + 1];
        float x0 = d[j][0] + b0, x1 = d[j][1] + b1;
        float x2 = d[j][2] + b0, x3 = d[j][3] + b1;
        if (ACT) {
            x0 = x0 / (1.f + __expf(-x0));
            x1 = x1 / (1.f + __expf(-x1));
            x2 = x2 / (1.f + __expf(-x2));
            x3 = x3 / (1.f + __expf(-x3));
        }
        uint32_t hw0, lw0, hw1, lw1;
        split2(x0, x1, hw0, lw0);
        split2(x2, x3, hw1, lw1);
        int w0 = r0 * (AST / 2) + c / 2;
        int w1 = (r0 + 8) * (AST / 2) + c / 2;
        Ahw[w0] = hw0; Alw[w0] = lw0;
        Ahw[w1] = hw1; Alw[w1] = lw1;
    }
    __syncthreads();
}

// ---------------------------------------------------------------------------
// fused kernel: per-block edge gather (phase 1) + MLP (phase 2)
// ---------------------------------------------------------------------------
__global__ __launch_bounds__(NT, 2) void node_kernel(
    const float* __restrict__ x,
    const float* __restrict__ W_rbf,
    const float* __restrict__ b_up, const float* __restrict__ b_lins,
    const float* __restrict__ W_out, float* __restrict__ out, int N)
{
    extern __shared__ char smem[];
    float* sBias = reinterpret_cast<float*>(smem + SM_BIAS);
    float* sRed  = reinterpret_cast<float*>(smem + SM_RED);
    const uint32_t smem_u32 = smem_to_u32(smem);

    const int tid = threadIdx.x;
    const int lane = tid & 31, warp = tid >> 5;
    const int g = lane >> 2, q = lane & 3;
    const int warp_m = warp & 3, warp_n = warp >> 2;
    const int node0 = blockIdx.x * MB;

    for (int t = tid; t < FEA; t += NT) {
        sBias[t]           = b_up[t];
        sBias[FEA + t]     = b_lins[t];
        sBias[2 * FEA + t] = b_lins[FEA + t];
        sBias[3 * FEA + t] = b_lins[2 * FEA + t];
        sBias[4 * FEA + t] = W_out[t];
    }

    // ---------------- phase 1: edge gather into Ah/Al ----------------
    {
        uint16_t* AhH = reinterpret_cast<uint16_t*>(smem + SM_AH);
        uint16_t* AlH = reinterpret_cast<uint16_t*>(smem + SM_AL);
        const int ch = tid;   // thread owns channel ch for all 64 rows

        // zero activation rows
#pragma unroll 8
        for (int r = 0; r < MB; r++) {
            AhH[r * AST + ch] = 0;
            AlH[r * AST + ch] = 0;
        }

        // W_rbf column for this channel
        float wr[6];
#pragma unroll
        for (int r = 0; r < 6; r++) wr[r] = W_rbf[r * HID + ch];

        const int hi_node = (node0 + MB < N) ? node0 + MB : N;
        const int estart = g_off[node0];
        const int eend   = g_off[hi_node];

        int*   sEid = reinterpret_cast<int*>(smem + SM_W);
        int*   sNid = sEid + 64;
        float* sRbf = reinterpret_cast<float*>(sNid + 64);

        int cur = -1;
        float acc = 0.f;

        for (int w0 = estart; w0 < eend; w0 += 64) {
            const int wm = (eend - w0 < 64) ? (eend - w0) : 64;
            __syncthreads();
            if (tid < 64) {
                if (tid < wm) {
                    sEid[tid] = g_sorted[w0 + tid];
                    sNid[tid] = g_nid[w0 + tid];
                }
            } else {
                int t = tid - 64;          // 0..191 -> float2 slots
                if (t * 2 < wm * 6)
                    *reinterpret_cast<float2*>(sRbf + t * 2) =
                        *reinterpret_cast<const float2*>(g_rbf_s + (size_t)w0 * 6 + t * 2);
            }
            __syncthreads();

            float xv[4];
#pragma unroll
            for (int p = 0; p < 4; p++)
                if (p < wm) xv[p] = x[(size_t)sEid[p] * HID + ch];

            for (int j = 0; j < wm; j++) {
                float v = xv[j & 3];
                if (j + 4 < wm) xv[j & 3] = x[(size_t)sEid[j + 4] * HID + ch];
                const float* rp = sRbf + j * 6;
                float gg = rp[0] * wr[0] + rp[1] * wr[1] + rp[2] * wr[2]
                         + rp[3] * wr[3] + rp[4] * wr[4] + rp[5] * wr[5];
                int nj = sNid[j];
                if (nj != cur) {
                    if (cur >= 0) {
                        uint16_t h, l;
                        split1(acc, h, l);
                        int r = cur - node0;
                        AhH[r * AST + ch] = h;
                        AlH[r * AST + ch] = l;
                    }
                    acc = 0.f;
                    cur = nj;
                }
                acc = fmaf(gg, v, acc);
            }
        }
        if (cur >= 0) {
            uint16_t h, l;
            split1(acc, h, l);
            int r = cur - node0;
            AhH[r * AST + ch] = h;
            AlH[r * AST + ch] = l;
        }
    }
    __syncthreads();

    // ---------------- phase 2: MLP ----------------
    float d[12][4];
    mloop<HID>(g_wh + L0_OFF, g_wl + L0_OFF, d, smem, smem_u32, tid, g, q, warp_m, warp_n);
    epi_store<false>(d, sBias, smem, g, q, warp_m, warp_n);
    mloop<FEA>(g_wh + L_OFF(1), g_wl + L_OFF(1), d, smem, smem_u32, tid, g, q, warp_m, warp_n);
    epi_store<true>(d, sBias + FEA, smem, g, q, warp_m, warp_n);
    mloop<FEA>(g_wh + L_OFF(2), g_wl + L_OFF(2), d, smem, smem_u32, tid, g, q, warp_m, warp_n);
    epi_store<true>(d, sBias + 2 * FEA, smem, g, q, warp_m, warp_n);
    mloop<FEA>(g_wh + L_OFF(3), g_wl + L_OFF(3), d, smem, smem_u32, tid, g, q, warp_m, warp_n);

    // final epilogue: silu + W_out projection fused
    {
        const float* sB3 = sBias + 3 * FEA;
        const float* sWo = sBias + 4 * FEA;
        float s0 = 0.f, s1 = 0.f;
#pragma unroll
        for (int j = 0; j < 12; j++) {
            int c = warp_n * 96 + j * 8 + q * 2;
            float b0 = sB3[c], b1 = sB3[c + 1];
            float w0 = sWo[c], w1 = sWo[c + 1];
            float x0 = d[j][0] + b0, x1 = d[j][1] + b1;
            float x2 = d[j][2] + b0, x3 = d[j][3] + b1;
            x0 = x0 / (1.f + __expf(-x0));
            x1 = x1 / (1.f + __expf(-x1));
            x2 = x2 / (1.f + __expf(-x2));
            x3 = x3 / (1.f + __expf(-x3));
            s0 += x0 * w0 + x1 * w1;
            s1 += x2 * w0 + x3 * w1;
        }
        s0 += __shfl_xor_sync(0xffffffffu, s0, 1);
        s0 += __shfl_xor_sync(0xffffffffu, s0, 2);
        s1 += __shfl_xor_sync(0xffffffffu, s1, 1);
        s1 += __shfl_xor_sync(0xffffffffu, s1, 2);
        const int r0 = warp_m * 16 + g;
        if (q == 0) {
            sRed[warp_n * MB + r0]     = s0;
            sRed[warp_n * MB + r0 + 8] = s1;
        }
        __syncthreads();
        if (tid < MB) {
            int node = node0 + tid;
            if (node < N) out[node] = sRed[tid] + sRed[MB + tid];
        }
    }
}

// ---------------------------------------------------------------------------
// launch
// ---------------------------------------------------------------------------
extern "C" void kernel_launch(void* const* d_in, const int* in_sizes, int n_in,
                              void* d_out, int out_size)
{
    const float* x    = (const float*)d_in[0];
    const float* rbf  = (const float*)d_in[1];
    const void*  idx  = d_in[2];
    const int wo = (n_in >= 10) ? 4 : 3;
    const float* W_rbf  = (const float*)d_in[wo + 0];
    const float* W_up   = (const float*)d_in[wo + 1];
    const float* b_up   = (const float*)d_in[wo + 2];
    const float* W_lins = (const float*)d_in[wo + 3];
    const float* b_lins = (const float*)d_in[wo + 4];
    const float* W_out  = (const float*)d_in[wo + 5];

    const int E = in_sizes[0] / HID;
    const int N = out_size;

    cudaFuncSetAttribute(node_kernel,
                         cudaFuncAttributeMaxDynamicSharedMemorySize, SM_TOT);

    detect_idx_kernel<<<1, 256>>>((const unsigned int*)idx, E);
    prep_kernel<<<(W_ELEMS + 255) / 256, 256>>>(W_up, W_lins);
    zero_cnt_kernel<<<(N + 255) / 256, 256>>>(N);
    hist_kernel<<<(E + 255) / 256, 256>>>(idx, E);
    scan_kernel<<<1, 1024>>>(N);
    scatter_kernel<<<(E + 255) / 256, 256>>>(idx, E);
    rbf_sort_kernel<<<(E + 255) / 256, 256>>>(rbf, E);
    node_kernel<<<(N + MB - 1) / MB, NT, SM_TOT>>>(
        x, W_rbf, b_up, b_lins, W_out, (float*)d_out, N);
}

// round 12
// speedup vs baseline: 1.3655x; 1.3655x over previous
#include <cuda_runtime.h>
#include <cuda_bf16.h>
#include <cstdint>

#define HID 256
#define FEA 192
#define NMAX 50000
#define EMAX 800000
#define MB 64           // nodes per block
#define NT 256          // threads per block

typedef unsigned long long ull;

// node kernel smem layout (bytes)
#define AST     264                        // act row stride in halfs (bank-perfect)
#define SM_AH   0
#define SM_AL   (MB * AST * 2)             // 33792
#define SM_W    (2 * MB * AST * 2)         // 67584 (weight chunk buffers)
#define CHUNK_B 6144                       // 192 cols * 32B (dense, conflict-free)
#define SM_BIAS (SM_W + 4 * CHUNK_B)       // 92160
#define SM_RED  (SM_BIAS + 5 * FEA * 4)    // 96000
#define SM_TOT  (SM_RED + 2 * MB * 4)      // 96512 -> 2 CTAs/SM

__device__ float g_xn[(size_t)NMAX * HID];
// CSR sort structures
__device__ int g_cnt[NMAX];
__device__ int g_off[NMAX + 1];
__device__ int g_cur[NMAX];
__device__ int g_sorted[EMAX];
__device__ int g_nid[EMAX];
// pre-split weights, chunked layout: [chunk16][n(192)][16 halfs, frag-order]
#define W_ELEMS (HID * FEA + 3 * FEA * FEA)
__device__ __align__(16) __nv_bfloat16 g_wh[W_ELEMS];
__device__ __align__(16) __nv_bfloat16 g_wl[W_ELEMS];
#define L0_OFF 0
#define L_OFF(l) (HID * FEA + ((l) - 1) * FEA * FEA)

// ---------------------------------------------------------------------------
// helpers
// ---------------------------------------------------------------------------
__device__ __forceinline__ void split1(float v, uint16_t& h, uint16_t& l) {
    __nv_bfloat16 hb = __float2bfloat16(v);
    float r = v - __bfloat162float(hb);
    __nv_bfloat16 lb = __float2bfloat16(r);
    h = __bfloat16_as_ushort(hb);
    l = __bfloat16_as_ushort(lb);
}
__device__ __forceinline__ void split2(float a, float b, uint32_t& hw, uint32_t& lw) {
    uint16_t ha, la, hb, lb;
    split1(a, ha, la);
    split1(b, hb, lb);
    hw = ((uint32_t)hb << 16) | ha;
    lw = ((uint32_t)lb << 16) | la;
}
__device__ __forceinline__ void mma_bf16(float* d,
                                         uint32_t a0, uint32_t a1, uint32_t a2, uint32_t a3,
                                         uint32_t b0, uint32_t b1) {
    asm volatile(
        "mma.sync.aligned.m16n8k16.row.col.f32.bf16.bf16.f32 "
        "{%0,%1,%2,%3}, {%4,%5,%6,%7}, {%8,%9}, {%0,%1,%2,%3};"
        : "+f"(d[0]), "+f"(d[1]), "+f"(d[2]), "+f"(d[3])
        : "r"(a0), "r"(a1), "r"(a2), "r"(a3), "r"(b0), "r"(b1));
}
__device__ __forceinline__ uint32_t smem_to_u32(const void* p) {
    uint32_t a;
    asm("{ .reg .u64 t; cvta.to.shared.u64 t, %1; cvt.u32.u64 %0, t; }"
        : "=r"(a) : "l"(p));
    return a;
}
__device__ __forceinline__ ull fma2(ull a, ull b, ull c) {
    ull d;
    asm("fma.rn.f32x2 %0, %1, %2, %3;" : "=l"(d) : "l"(a), "l"(b), "l"(c));
    return d;
}
__device__ __forceinline__ ull mul2(ull a, ull b) {
    ull d;
    asm("mul.rn.f32x2 %0, %1, %2;" : "=l"(d) : "l"(a), "l"(b));
    return d;
}
__device__ __forceinline__ ull packf2(float lo, float hi) {
    ull d;
    asm("mov.b64 %0, {%1, %2};" : "=l"(d) : "f"(lo), "f"(hi));
    return d;
}
__device__ __forceinline__ void unpackf2(ull v, float& lo, float& hi) {
    asm("mov.b64 {%0, %1}, %2;" : "=f"(lo), "=f"(hi) : "l"(v));
}
// block-local int64-vs-int32 index detection (checks first 512 entries)
__device__ __forceinline__ int block_detect_is64(const void* idx, int E, int tid) {
    __shared__ int bad;
    if (tid == 0) bad = 0;
    __syncthreads();
    int n = E < 512 ? E : 512;
    const unsigned int* w = reinterpret_cast<const unsigned int*>(idx);
    for (int k = tid; k < n; k += NT)
        if (w[2 * k + 1] != 0u) bad = 1;
    __syncthreads();
    return !bad;
}
__device__ __forceinline__ int load_idx(const void* idx, int e, int is64) {
    return is64 ? (int)reinterpret_cast<const long long*>(idx)[e]
                : reinterpret_cast<const int*>(idx)[e];
}

// ---------------------------------------------------------------------------
// prep: split weights to bf16 hi/lo in mma-fragment half order; zero g_cnt
// half order within a 16-kk chunk: p = ((kk&7)>>1)*4 + ((kk>>3)&1)*2 + (kk&1)
// so thread q's LDS.64 at word n*8+q*2 yields (b0,b1) directly.
// ---------------------------------------------------------------------------
__global__ void prep_kernel(const float* __restrict__ W_up,
                            const float* __restrict__ W_lins) {
    int t = blockIdx.x * blockDim.x + threadIdx.x;
    if (t < NMAX) g_cnt[t] = 0;
    if (t >= W_ELEMS) return;
    int base, el;
    const float* src;
    if (t < HID * FEA) { base = L0_OFF; el = t; src = W_up; }
    else {
        int t2 = t - HID * FEA;
        int l = t2 / (FEA * FEA);
        base = L_OFF(l + 1);
        el = t2 - l * FEA * FEA;
        src = W_lins + l * FEA * FEA;
    }
    int kf = el / FEA, n = el - kf * FEA;
    uint16_t h, l16;
    split1(src[kf * FEA + n], h, l16);
    int kk = kf & 15;
    int p = (((kk & 7) >> 1) << 2) | (((kk >> 3) & 1) << 1) | (kk & 1);
    int dst = base + (kf >> 4) * (16 * FEA) + n * 16 + p;
    g_wh[dst] = __ushort_as_bfloat16(h);
    g_wl[dst] = __ushort_as_bfloat16(l16);
}

// ---------------------------------------------------------------------------
// sort chain
// ---------------------------------------------------------------------------
__global__ __launch_bounds__(NT) void hist_kernel(const void* __restrict__ idx, int E) {
    int is64 = block_detect_is64(idx, E, threadIdx.x);
    int e = blockIdx.x * blockDim.x + threadIdx.x;
    if (e >= E) return;
    atomicAdd(&g_cnt[load_idx(idx, e, is64)], 1);
}

__global__ __launch_bounds__(1024) void scan_kernel(int N) {
    __shared__ int part[1024];
    const int tid = threadIdx.x;
    const int chunk = (N + 1023) / 1024;
    const int base = tid * chunk;
    int s = 0;
    for (int k = 0; k < chunk; k++) {
        int i = base + k;
        if (i < N) s += g_cnt[i];
    }
    part[tid] = s;
    __syncthreads();
    for (int d = 1; d < 1024; d <<= 1) {
        int v = (tid >= d) ? part[tid - d] : 0;
        __syncthreads();
        part[tid] += v;
        __syncthreads();
    }
    int run = part[tid] - s;
    for (int k = 0; k < chunk; k++) {
        int i = base + k;
        if (i < N) {
            g_off[i] = run;
            g_cur[i] = run;
            run += g_cnt[i];
        }
    }
    if (tid == 1023) g_off[N] = part[1023];
}

__global__ __launch_bounds__(NT) void scatter_kernel(const void* __restrict__ idx, int E) {
    int is64 = block_detect_is64(idx, E, threadIdx.x);
    int e = blockIdx.x * blockDim.x + threadIdx.x;
    if (e >= E) return;
    int n = load_idx(idx, e, is64);
    int p = atomicAdd(&g_cur[n], 1);
    g_sorted[p] = e;
    g_nid[p] = n;
}

// ---------------------------------------------------------------------------
// ownership gather: warp owns every node whose first edge lies in its 32-edge
// chunk; skips leading continuation edges, extends past the boundary to finish
// its last node. Every node written by exactly ONE warp -> plain STG.
// ---------------------------------------------------------------------------
__global__ __launch_bounds__(256) void gather_kernel(
    const float* __restrict__ x, const float* __restrict__ rbf,
    const float* __restrict__ W_rbf, int E)
{
    const int chunk = (blockIdx.x * blockDim.x + threadIdx.x) >> 5;
    const int lane = threadIdx.x & 31;
    const int c0 = chunk * 32;
    if (c0 >= E) return;

    // windows (coalesced)
    const bool inb = (c0 + lane) < E;
    const int nid0 = inb ? g_nid[c0 + lane] : -1;
    const int eid0 = inb ? g_sorted[c0 + lane] : 0;
    const int prev = (c0 > 0) ? g_nid[c0 - 1] : -1;

    unsigned startmask = __ballot_sync(0xffffffffu, !inb || nid0 != prev);
    if (!startmask) return;                       // whole chunk is continuation
    const int jstart = c0 + __ffs(startmask) - 1;

    const int jend0 = (c0 + 32 < E) ? c0 + 32 : E;
    if (jstart >= jend0) return;
    int jend = jend0;
    {
        int lastn = __shfl_sync(0xffffffffu, nid0, jend0 - 1 - c0);
        if (jend0 < E) {
            int base = jend0;
            while (true) {
                int nv = (base + lane < E) ? g_nid[base + lane] : -9;
                unsigned mb = __ballot_sync(0xffffffffu, nv != lastn);
                if (mb) { jend = base + __ffs(mb) - 1; break; }
                base += 32;
                if (base >= E) { jend = E; break; }
            }
        }
    }

    // W_rbf columns for this lane's 8 channels, packed f32x2
    ull wp[6][4];
#pragma unroll
    for (int r = 0; r < 6; r++) {
        float4 a = *reinterpret_cast<const float4*>(W_rbf + r * HID + lane * 8);
        float4 b = *reinterpret_cast<const float4*>(W_rbf + r * HID + lane * 8 + 4);
        wp[r][0] = packf2(a.x, a.y);
        wp[r][1] = packf2(a.z, a.w);
        wp[r][2] = packf2(b.x, b.y);
        wp[r][3] = packf2(b.z, b.w);
    }

    auto get_e = [&](int j) -> int {
        int rel = j - c0;
        return (rel < 32) ? __shfl_sync(0xffffffffu, eid0, rel) : g_sorted[j];
    };
    auto get_n = [&](int j) -> int {
        int rel = j - c0;
        return (rel < 32) ? __shfl_sync(0xffffffffu, nid0, rel) : g_nid[j];
    };

    ull acc[4] = {0ULL, 0ULL, 0ULL, 0ULL};
    ulonglong2 ax0, ax1, bx0, bx1;
    float2 ar0, ar1, ar2, br0, br1, br2;

    auto loadS = [&](int e, ulonglong2& x0, ulonglong2& x1,
                     float2& r0, float2& r1, float2& r2) {
        const ulonglong2* xp =
            reinterpret_cast<const ulonglong2*>(x + (size_t)e * HID + lane * 8);
        x0 = xp[0];
        x1 = xp[1];
        const float2* rp = reinterpret_cast<const float2*>(rbf + (size_t)e * 6);
        r0 = rp[0];
        r1 = rp[1];
        r2 = rp[2];
    };
    auto computeS = [&](const ulonglong2& x0, const ulonglong2& x1,
                        const float2& r0, const float2& r1, const float2& r2) {
        ull q0 = packf2(r0.x, r0.x), q1 = packf2(r0.y, r0.y);
        ull q2 = packf2(r1.x, r1.x), q3 = packf2(r1.y, r1.y);
        ull q4 = packf2(r2.x, r2.x), q5 = packf2(r2.y, r2.y);
        ull xv[4] = {x0.x, x0.y, x1.x, x1.y};
#pragma unroll
        for (int p = 0; p < 4; p++) {
            ull g = mul2(q0, wp[0][p]);
            g = fma2(q1, wp[1][p], g);
            g = fma2(q2, wp[2][p], g);
            g = fma2(q3, wp[3][p], g);
            g = fma2(q4, wp[4][p], g);
            g = fma2(q5, wp[5][p], g);
            acc[p] = fma2(g, xv[p], acc[p]);
        }
    };
    auto flush = [&](int node) {
        float f0, f1, f2, f3, f4, f5, f6, f7;
        unpackf2(acc[0], f0, f1);
        unpackf2(acc[1], f2, f3);
        unpackf2(acc[2], f4, f5);
        unpackf2(acc[3], f6, f7);
        float4* dst = reinterpret_cast<float4*>(g_xn + (size_t)node * HID + lane * 8);
        dst[0] = make_float4(f0, f1, f2, f3);
        dst[1] = make_float4(f4, f5, f6, f7);
        acc[0] = acc[1] = acc[2] = acc[3] = 0ULL;
    };

    int cur = get_n(jstart);
    loadS(get_e(jstart), ax0, ax1, ar0, ar1, ar2);
    if (jstart + 1 < jend)
        loadS(get_e(jstart + 1), bx0, bx1, br0, br1, br2);

    for (int j = jstart; j < jend; j++) {
        int nj = get_n(j);
        if (nj != cur) { flush(cur); cur = nj; }
        if (((j - jstart) & 1) == 0) {
            computeS(ax0, ax1, ar0, ar1, ar2);
            if (j + 2 < jend) loadS(get_e(j + 2), ax0, ax1, ar0, ar1, ar2);
        } else {
            computeS(bx0, bx1, br0, br1, br2);
            if (j + 2 < jend) loadS(get_e(j + 2), bx0, bx1, br0, br1, br2);
        }
    }
    flush(cur);
}

// ---------------------------------------------------------------------------
// node MLP: mma.sync bf16 3-term split; conflict-free vectorized B loads
// ---------------------------------------------------------------------------
__device__ __forceinline__ void stage_chunk(
    const __nv_bfloat16* __restrict__ Wh, const __nv_bfloat16* __restrict__ Wl,
    int s, int buf, uint32_t smem_u32, int tid)
{
    const char* srcH = reinterpret_cast<const char*>(Wh + s * 16 * FEA);
    const char* srcL = reinterpret_cast<const char*>(Wl + s * 16 * FEA);
#pragma unroll
    for (int it = 0; it < 3; it++) {
        int t = tid + it * NT;                // 0..767
        int term = t >= 384;
        int u = term ? t - 384 : t;           // 0..383
        int n = u >> 1, seg = u & 1;
        const char* src = (term ? srcL : srcH) + n * 32 + seg * 16;
        uint32_t dst = smem_u32 + SM_W + term * (2 * CHUNK_B) + buf * CHUNK_B
                     + n * 32 + seg * 16;
        asm volatile("cp.async.cg.shared.global [%0], [%1], 16;"
                     :: "r"(dst), "l"(src));
    }
    asm volatile("cp.async.commit_group;");
}

template<int K>
__device__ __forceinline__ void mloop(
    const __nv_bfloat16* __restrict__ Wh, const __nv_bfloat16* __restrict__ Wl,
    float (&d)[12][4], char* smem, uint32_t smem_u32,
    int tid, int g, int q, int warp_m, int warp_n)
{
#pragma unroll
    for (int j = 0; j < 12; j++)
#pragma unroll
        for (int u = 0; u < 4; u++) d[j][u] = 0.f;

    stage_chunk(Wh, Wl, 0, 0, smem_u32, tid);

    const uint32_t* Ahw = reinterpret_cast<const uint32_t*>(smem + SM_AH);
    const uint32_t* Alw = reinterpret_cast<const uint32_t*>(smem + SM_AL);
    const int r0 = warp_m * 16 + g;
    constexpr int S = K / 16;

#pragma unroll 2
    for (int s = 0; s < S; s++) {
        const int b = s & 1;
        if (s + 1 < S) {
            stage_chunk(Wh, Wl, s + 1, b ^ 1, smem_u32, tid);
            asm volatile("cp.async.wait_group 1;");
        } else {
            asm volatile("cp.async.wait_group 0;");
        }
        __syncthreads();

        const int base = r0 * (AST / 2) + s * 8 + q;
        uint32_t ah[4], al[4];
        ah[0] = Ahw[base];
        ah[1] = Ahw[base + 8 * (AST / 2)];
        ah[2] = Ahw[base + 4];
        ah[3] = Ahw[base + 8 * (AST / 2) + 4];
        al[0] = Alw[base];
        al[1] = Alw[base + 8 * (AST / 2)];
        al[2] = Alw[base + 4];
        al[3] = Alw[base + 8 * (AST / 2) + 4];

        // conflict-free LDS.64 B loads: word64 index = n*4 + q
        const uint2* bhp = reinterpret_cast<const uint2*>(smem + SM_W + b * CHUNK_B);
        const uint2* blp = reinterpret_cast<const uint2*>(smem + SM_W + 2 * CHUNK_B + b * CHUNK_B);
#pragma unroll
        for (int j = 0; j < 12; j++) {
            int n = warp_n * 96 + j * 8 + g;
            uint2 bh = bhp[n * 4 + q];
            uint2 bl = blp[n * 4 + q];
            mma_bf16(d[j], ah[0], ah[1], ah[2], ah[3], bh.x, bh.y);
            mma_bf16(d[j], al[0], al[1], al[2], al[3], bh.x, bh.y);
            mma_bf16(d[j], ah[0], ah[1], ah[2], ah[3], bl.x, bl.y);
        }
        __syncthreads();
    }
}

template<bool ACT>
__device__ __forceinline__ void epi_store(
    float (&d)[12][4], const float* __restrict__ bias,
    char* smem, int g, int q, int warp_m, int warp_n)
{
    uint32_t* Ahw = reinterpret_cast<uint32_t*>(smem + SM_AH);
    uint32_t* Alw = reinterpret_cast<uint32_t*>(smem + SM_AL);
    const int r0 = warp_m * 16 + g;
#pragma unroll
    for (int j = 0; j < 12; j++) {
        int c = warp_n * 96 + j * 8 + q * 2;
        float b0 = bias[c], b1 = bias[c + 1];
        float x0 = d[j][0] + b0, x1 = d[j][1] + b1;
        float x2 = d[j][2] + b0, x3 = d[j][3] + b1;
        if (ACT) {
            x0 = x0 / (1.f + __expf(-x0));
            x1 = x1 / (1.f + __expf(-x1));
            x2 = x2 / (1.f + __expf(-x2));
            x3 = x3 / (1.f + __expf(-x3));
        }
        uint32_t hw0, lw0, hw1, lw1;
        split2(x0, x1, hw0, lw0);
        split2(x2, x3, hw1, lw1);
        int w0 = r0 * (AST / 2) + c / 2;
        int w1 = (r0 + 8) * (AST / 2) + c / 2;
        Ahw[w0] = hw0; Alw[w0] = lw0;
        Ahw[w1] = hw1; Alw[w1] = lw1;
    }
    __syncthreads();
}

__global__ __launch_bounds__(NT, 2) void node_kernel(
    const float* __restrict__ b_up, const float* __restrict__ b_lins,
    const float* __restrict__ W_out, float* __restrict__ out, int N)
{
    extern __shared__ char smem[];
    float* sBias = reinterpret_cast<float*>(smem + SM_BIAS);
    float* sRed  = reinterpret_cast<float*>(smem + SM_RED);
    const uint32_t smem_u32 = smem_to_u32(smem);

    const int tid = threadIdx.x;
    const int lane = tid & 31, warp = tid >> 5;
    const int g = lane >> 2, q = lane & 3;
    const int warp_m = warp & 3, warp_n = warp >> 2;
    const int node0 = blockIdx.x * MB;

    for (int t = tid; t < FEA; t += NT) {
        sBias[t]           = b_up[t];
        sBias[FEA + t]     = b_lins[t];
        sBias[2 * FEA + t] = b_lins[FEA + t];
        sBias[3 * FEA + t] = b_lins[2 * FEA + t];
        sBias[4 * FEA + t] = W_out[t];
    }
    // load xn tile [64][256] -> Ah/Al bf16 hi/lo (empty nodes -> zeros)
    {
        uint32_t* Ahw = reinterpret_cast<uint32_t*>(smem + SM_AH);
        uint32_t* Alw = reinterpret_cast<uint32_t*>(smem + SM_AL);
        const int row = tid >> 2, part = tid & 3;
        const int node = node0 + row;
        bool valid = false;
        if (node < N) valid = (g_off[node] != g_off[node + 1]);
        const float4* src = reinterpret_cast<const float4*>(
            g_xn + (size_t)node * HID + part * 64);
#pragma unroll
        for (int u = 0; u < 16; u++) {
            float4 v = valid ? src[u] : make_float4(0.f, 0.f, 0.f, 0.f);
            uint32_t hw0, lw0, hw1, lw1;
            split2(v.x, v.y, hw0, lw0);
            split2(v.z, v.w, hw1, lw1);
            int w = row * (AST / 2) + part * 32 + u * 2;
            Ahw[w] = hw0;     Alw[w] = lw0;
            Ahw[w + 1] = hw1; Alw[w + 1] = lw1;
        }
    }
    __syncthreads();

    float d[12][4];
    mloop<HID>(g_wh + L0_OFF, g_wl + L0_OFF, d, smem, smem_u32, tid, g, q, warp_m, warp_n);
    epi_store<false>(d, sBias, smem, g, q, warp_m, warp_n);
    mloop<FEA>(g_wh + L_OFF(1), g_wl + L_OFF(1), d, smem, smem_u32, tid, g, q, warp_m, warp_n);
    epi_store<true>(d, sBias + FEA, smem, g, q, warp_m, warp_n);
    mloop<FEA>(g_wh + L_OFF(2), g_wl + L_OFF(2), d, smem, smem_u32, tid, g, q, warp_m, warp_n);
    epi_store<true>(d, sBias + 2 * FEA, smem, g, q, warp_m, warp_n);
    mloop<FEA>(g_wh + L_OFF(3), g_wl + L_OFF(3), d, smem, smem_u32, tid, g, q, warp_m, warp_n);

    // final epilogue: silu + W_out projection fused
    {
        const float* sB3 = sBias + 3 * FEA;
        const float* sWo = sBias + 4 * FEA;
        float s0 = 0.f, s1 = 0.f;
#pragma unroll
        for (int j = 0; j < 12; j++) {
            int c = warp_n * 96 + j * 8 + q * 2;
            float b0 = sB3[c], b1 = sB3[c + 1];
            float w0 = sWo[c], w1 = sWo[c + 1];
            float x0 = d[j][0] + b0, x1 = d[j][1] + b1;
            float x2 = d[j][2] + b0, x3 = d[j][3] + b1;
            x0 = x0 / (1.f + __expf(-x0));
            x1 = x1 / (1.f + __expf(-x1));
            x2 = x2 / (1.f + __expf(-x2));
            x3 = x3 / (1.f + __expf(-x3));
            s0 += x0 * w0 + x1 * w1;
            s1 += x2 * w0 + x3 * w1;
        }
        s0 += __shfl_xor_sync(0xffffffffu, s0, 1);
        s0 += __shfl_xor_sync(0xffffffffu, s0, 2);
        s1 += __shfl_xor_sync(0xffffffffu, s1, 1);
        s1 += __shfl_xor_sync(0xffffffffu, s1, 2);
        const int r0 = warp_m * 16 + g;
        if (q == 0) {
            sRed[warp_n * MB + r0]     = s0;
            sRed[warp_n * MB + r0 + 8] = s1;
        }
        __syncthreads();
        if (tid < MB) {
            int node = node0 + tid;
            if (node < N) out[node] = sRed[tid] + sRed[MB + tid];
        }
    }
}

// ---------------------------------------------------------------------------
// launch
// ---------------------------------------------------------------------------
extern "C" void kernel_launch(void* const* d_in, const int* in_sizes, int n_in,
                              void* d_out, int out_size)
{
    const float* x    = (const float*)d_in[0];
    const float* rbf  = (const float*)d_in[1];
    const void*  idx  = d_in[2];
    const int wo = (n_in >= 10) ? 4 : 3;
    const float* W_rbf  = (const float*)d_in[wo + 0];
    const float* W_up   = (const float*)d_in[wo + 1];
    const float* b_up   = (const float*)d_in[wo + 2];
    const float* W_lins = (const float*)d_in[wo + 3];
    const float* b_lins = (const float*)d_in[wo + 4];
    const float* W_out  = (const float*)d_in[wo + 5];

    const int E = in_sizes[0] / HID;
    const int N = out_size;

    cudaFuncSetAttribute(node_kernel,
                         cudaFuncAttributeMaxDynamicSharedMemorySize, SM_TOT);

    prep_kernel<<<(W_ELEMS + 255) / 256, 256>>>(W_up, W_lins);
    hist_kernel<<<(E + 255) / 256, 256>>>(idx, E);
    scan_kernel<<<1, 1024>>>(N);
    scatter_kernel<<<(E + 255) / 256, 256>>>(idx, E);
    const int nchunks = (E + 31) / 32;
    gather_kernel<<<(nchunks + 7) / 8, 256>>>(x, rbf, W_rbf, E);
    node_kernel<<<(N + MB - 1) / MB, NT, SM_TOT>>>(
        b_up, b_lins, W_out, (float*)d_out, N);
}

// round 13
// speedup vs baseline: 1.7520x; 1.2831x over previous
#include <cuda_runtime.h>
#include <cuda_bf16.h>
#include <cstdint>

#define HID 256
#define FEA 192
#define NMAX 50000
#define EMAX 800000
#define MB 64           // nodes per block
#define NT 256          // threads per block

typedef unsigned long long ull;

// node kernel smem layout (bytes)
#define AST     264                        // act row stride in halfs (bank-perfect)
#define SM_AH   0
#define SM_AL   (MB * AST * 2)             // 33792
#define SM_W    (2 * MB * AST * 2)         // 67584 (weight chunk buffers)
#define CHUNK_B 6144                       // 192 cols * 32B (dense, conflict-free)
#define SM_BIAS (SM_W + 4 * CHUNK_B)       // 92160
#define SM_RED  (SM_BIAS + 5 * FEA * 4)    // 96000
#define SM_TOT  (SM_RED + 2 * MB * 4)      // 96512 -> 2 CTAs/SM

__device__ float g_xn[(size_t)NMAX * HID];
// CSR sort structures
__device__ int g_cnt[NMAX];
__device__ int g_off[NMAX + 1];
__device__ int g_cur[NMAX];
__device__ int g_sorted[EMAX];
__device__ int g_nid[EMAX];
// pre-split weights, chunked layout: [chunk16][n(192)][16 halfs, frag-order]
#define W_ELEMS (HID * FEA + 3 * FEA * FEA)
__device__ __align__(16) __nv_bfloat16 g_wh[W_ELEMS];
__device__ __align__(16) __nv_bfloat16 g_wl[W_ELEMS];
#define L0_OFF 0
#define L_OFF(l) (HID * FEA + ((l) - 1) * FEA * FEA)

// ---------------------------------------------------------------------------
// helpers
// ---------------------------------------------------------------------------
__device__ __forceinline__ void split1(float v, uint16_t& h, uint16_t& l) {
    __nv_bfloat16 hb = __float2bfloat16(v);
    float r = v - __bfloat162float(hb);
    __nv_bfloat16 lb = __float2bfloat16(r);
    h = __bfloat16_as_ushort(hb);
    l = __bfloat16_as_ushort(lb);
}
__device__ __forceinline__ void split2(float a, float b, uint32_t& hw, uint32_t& lw) {
    uint16_t ha, la, hb, lb;
    split1(a, ha, la);
    split1(b, hb, lb);
    hw = ((uint32_t)hb << 16) | ha;
    lw = ((uint32_t)lb << 16) | la;
}
__device__ __forceinline__ void mma_bf16(float* d,
                                         uint32_t a0, uint32_t a1, uint32_t a2, uint32_t a3,
                                         uint32_t b0, uint32_t b1) {
    asm volatile(
        "mma.sync.aligned.m16n8k16.row.col.f32.bf16.bf16.f32 "
        "{%0,%1,%2,%3}, {%4,%5,%6,%7}, {%8,%9}, {%0,%1,%2,%3};"
        : "+f"(d[0]), "+f"(d[1]), "+f"(d[2]), "+f"(d[3])
        : "r"(a0), "r"(a1), "r"(a2), "r"(a3), "r"(b0), "r"(b1));
}
__device__ __forceinline__ uint32_t smem_to_u32(const void* p) {
    uint32_t a;
    asm("{ .reg .u64 t; cvta.to.shared.u64 t, %1; cvt.u32.u64 %0, t; }"
        : "=r"(a) : "l"(p));
    return a;
}
__device__ __forceinline__ ull fma2(ull a, ull b, ull c) {
    ull d;
    asm("fma.rn.f32x2 %0, %1, %2, %3;" : "=l"(d) : "l"(a), "l"(b), "l"(c));
    return d;
}
__device__ __forceinline__ ull mul2(ull a, ull b) {
    ull d;
    asm("mul.rn.f32x2 %0, %1, %2;" : "=l"(d) : "l"(a), "l"(b));
    return d;
}
__device__ __forceinline__ ull packf2(float lo, float hi) {
    ull d;
    asm("mov.b64 %0, {%1, %2};" : "=l"(d) : "f"(lo), "f"(hi));
    return d;
}
__device__ __forceinline__ void unpackf2(ull v, float& lo, float& hi) {
    asm("mov.b64 {%0, %1}, %2;" : "=f"(lo), "=f"(hi) : "l"(v));
}
// block-local int64-vs-int32 index detection (checks first 512 entries)
__device__ __forceinline__ int block_detect_is64(const void* idx, int E, int tid) {
    __shared__ int bad;
    if (tid == 0) bad = 0;
    __syncthreads();
    int n = E < 512 ? E : 512;
    const unsigned int* w = reinterpret_cast<const unsigned int*>(idx);
    for (int k = tid; k < n; k += NT)
        if (w[2 * k + 1] != 0u) bad = 1;
    __syncthreads();
    return !bad;
}
__device__ __forceinline__ int load_idx(const void* idx, int e, int is64) {
    return is64 ? (int)reinterpret_cast<const long long*>(idx)[e]
                : reinterpret_cast<const int*>(idx)[e];
}

// ---------------------------------------------------------------------------
// prep: split weights to bf16 hi/lo in mma-fragment half order; zero g_cnt
// ---------------------------------------------------------------------------
__global__ void prep_kernel(const float* __restrict__ W_up,
                            const float* __restrict__ W_lins) {
    int t = blockIdx.x * blockDim.x + threadIdx.x;
    if (t < NMAX) g_cnt[t] = 0;
    if (t >= W_ELEMS) return;
    int base, el;
    const float* src;
    if (t < HID * FEA) { base = L0_OFF; el = t; src = W_up; }
    else {
        int t2 = t - HID * FEA;
        int l = t2 / (FEA * FEA);
        base = L_OFF(l + 1);
        el = t2 - l * FEA * FEA;
        src = W_lins + l * FEA * FEA;
    }
    int kf = el / FEA, n = el - kf * FEA;
    uint16_t h, l16;
    split1(src[kf * FEA + n], h, l16);
    int kk = kf & 15;
    int p = (((kk & 7) >> 1) << 2) | (((kk >> 3) & 1) << 1) | (kk & 1);
    int dst = base + (kf >> 4) * (16 * FEA) + n * 16 + p;
    g_wh[dst] = __ushort_as_bfloat16(h);
    g_wl[dst] = __ushort_as_bfloat16(l16);
}

// ---------------------------------------------------------------------------
// sort chain
// ---------------------------------------------------------------------------
__global__ void zero_xn_kernel(int n4) {
    float4* p = reinterpret_cast<float4*>(g_xn);
    const float4 z = make_float4(0.f, 0.f, 0.f, 0.f);
    for (int i = blockIdx.x * blockDim.x + threadIdx.x; i < n4;
         i += gridDim.x * blockDim.x)
        p[i] = z;
}

__global__ __launch_bounds__(NT) void hist_kernel(const void* __restrict__ idx, int E) {
    int is64 = block_detect_is64(idx, E, threadIdx.x);
    int e = blockIdx.x * blockDim.x + threadIdx.x;
    if (e >= E) return;
    atomicAdd(&g_cnt[load_idx(idx, e, is64)], 1);
}

__global__ __launch_bounds__(1024) void scan_kernel(int N) {
    __shared__ int part[1024];
    const int tid = threadIdx.x;
    const int chunk = (N + 1023) / 1024;
    const int base = tid * chunk;
    int s = 0;
    for (int k = 0; k < chunk; k++) {
        int i = base + k;
        if (i < N) s += g_cnt[i];
    }
    part[tid] = s;
    __syncthreads();
    for (int d = 1; d < 1024; d <<= 1) {
        int v = (tid >= d) ? part[tid - d] : 0;
        __syncthreads();
        part[tid] += v;
        __syncthreads();
    }
    int run = part[tid] - s;
    for (int k = 0; k < chunk; k++) {
        int i = base + k;
        if (i < N) {
            g_off[i] = run;
            g_cur[i] = run;
            run += g_cnt[i];
        }
    }
    if (tid == 1023) g_off[N] = part[1023];
}

__global__ __launch_bounds__(NT) void scatter_kernel(const void* __restrict__ idx, int E) {
    int is64 = block_detect_is64(idx, E, threadIdx.x);
    int e = blockIdx.x * blockDim.x + threadIdx.x;
    if (e >= E) return;
    int n = load_idx(idx, e, is64);
    int p = atomicAdd(&g_cur[n], 1);
    g_sorted[p] = e;
    g_nid[p] = n;
}

// ---------------------------------------------------------------------------
// chunk-parallel gather with segmented red.v4 flush (R8 structure,
// coalesced g_nid staging)
// ---------------------------------------------------------------------------
__global__ __launch_bounds__(256) void gather_kernel(
    const float* __restrict__ x, const float* __restrict__ rbf,
    const float* __restrict__ W_rbf, int E)
{
    const int chunk = (blockIdx.x * blockDim.x + threadIdx.x) >> 5;
    const int lane = threadIdx.x & 31;
    const int c0 = chunk * 32;
    if (c0 >= E) return;
    int m = E - c0;
    if (m > 32) m = 32;

    // W_rbf columns for this lane's 8 channels, packed f32x2
    ull wp[6][4];
#pragma unroll
    for (int r = 0; r < 6; r++) {
        float4 a = *reinterpret_cast<const float4*>(W_rbf + r * HID + lane * 8);
        float4 b = *reinterpret_cast<const float4*>(W_rbf + r * HID + lane * 8 + 4);
        wp[r][0] = packf2(a.x, a.y);
        wp[r][1] = packf2(a.z, a.w);
        wp[r][2] = packf2(b.x, b.y);
        wp[r][3] = packf2(b.z, b.w);
    }

    const int li = lane < m ? lane : m - 1;
    const int eid = g_sorted[c0 + li];
    const int nid = g_nid[c0 + li];

    ull acc[4] = {0ULL, 0ULL, 0ULL, 0ULL};
    int cur = __shfl_sync(0xffffffffu, nid, 0);

    ulonglong2 ax0, ax1, bx0, bx1;
    float2 ar0, ar1, ar2, br0, br1, br2;

    auto loadS = [&](int e, ulonglong2& x0, ulonglong2& x1,
                     float2& r0, float2& r1, float2& r2) {
        const ulonglong2* xp =
            reinterpret_cast<const ulonglong2*>(x + (size_t)e * HID + lane * 8);
        x0 = xp[0];
        x1 = xp[1];
        const float2* rp = reinterpret_cast<const float2*>(rbf + (size_t)e * 6);
        r0 = rp[0];
        r1 = rp[1];
        r2 = rp[2];
    };
    auto computeS = [&](const ulonglong2& x0, const ulonglong2& x1,
                        const float2& r0, const float2& r1, const float2& r2) {
        ull q0 = packf2(r0.x, r0.x), q1 = packf2(r0.y, r0.y);
        ull q2 = packf2(r1.x, r1.x), q3 = packf2(r1.y, r1.y);
        ull q4 = packf2(r2.x, r2.x), q5 = packf2(r2.y, r2.y);
        ull xv[4] = {x0.x, x0.y, x1.x, x1.y};
#pragma unroll
        for (int p = 0; p < 4; p++) {
            ull g = mul2(q0, wp[0][p]);
            g = fma2(q1, wp[1][p], g);
            g = fma2(q2, wp[2][p], g);
            g = fma2(q3, wp[3][p], g);
            g = fma2(q4, wp[4][p], g);
            g = fma2(q5, wp[5][p], g);
            acc[p] = fma2(g, xv[p], acc[p]);
        }
    };
    auto flush = [&](int node) {
        float f0, f1, f2, f3, f4, f5, f6, f7;
        unpackf2(acc[0], f0, f1);
        unpackf2(acc[1], f2, f3);
        unpackf2(acc[2], f4, f5);
        unpackf2(acc[3], f6, f7);
        float* p = g_xn + (size_t)node * HID + lane * 8;
        asm volatile("red.global.add.v4.f32 [%0], {%1, %2, %3, %4};"
                     :: "l"(p), "f"(f0), "f"(f1), "f"(f2), "f"(f3) : "memory");
        asm volatile("red.global.add.v4.f32 [%0], {%1, %2, %3, %4};"
                     :: "l"(p + 4), "f"(f4), "f"(f5), "f"(f6), "f"(f7) : "memory");
        acc[0] = acc[1] = acc[2] = acc[3] = 0ULL;
    };

    {
        int e0 = __shfl_sync(0xffffffffu, eid, 0);
        loadS(e0, ax0, ax1, ar0, ar1, ar2);
    }
    if (m > 1) {
        int e1 = __shfl_sync(0xffffffffu, eid, 1);
        loadS(e1, bx0, bx1, br0, br1, br2);
    }

    for (int j = 0; j < m; j++) {
        int nj = __shfl_sync(0xffffffffu, nid, j);
        if (nj != cur) { flush(cur); cur = nj; }
        if ((j & 1) == 0) {
            computeS(ax0, ax1, ar0, ar1, ar2);
            if (j + 2 < m) {
                int en = __shfl_sync(0xffffffffu, eid, j + 2);
                loadS(en, ax0, ax1, ar0, ar1, ar2);
            }
        } else {
            computeS(bx0, bx1, br0, br1, br2);
            if (j + 2 < m) {
                int en = __shfl_sync(0xffffffffu, eid, j + 2);
                loadS(en, bx0, bx1, br0, br1, br2);
            }
        }
    }
    flush(cur);
}

// ---------------------------------------------------------------------------
// node MLP: mma.sync bf16 3-term split; conflict-free vectorized B loads
// ---------------------------------------------------------------------------
__device__ __forceinline__ void stage_chunk(
    const __nv_bfloat16* __restrict__ Wh, const __nv_bfloat16* __restrict__ Wl,
    int s, int buf, uint32_t smem_u32, int tid)
{
    const char* srcH = reinterpret_cast<const char*>(Wh + s * 16 * FEA);
    const char* srcL = reinterpret_cast<const char*>(Wl + s * 16 * FEA);
#pragma unroll
    for (int it = 0; it < 3; it++) {
        int t = tid + it * NT;                // 0..767
        int term = t >= 384;
        int u = term ? t - 384 : t;           // 0..383
        int n = u >> 1, seg = u & 1;
        const char* src = (term ? srcL : srcH) + n * 32 + seg * 16;
        uint32_t dst = smem_u32 + SM_W + term * (2 * CHUNK_B) + buf * CHUNK_B
                     + n * 32 + seg * 16;
        asm volatile("cp.async.cg.shared.global [%0], [%1], 16;"
                     :: "r"(dst), "l"(src));
    }
    asm volatile("cp.async.commit_group;");
}

template<int K>
__device__ __forceinline__ void mloop(
    const __nv_bfloat16* __restrict__ Wh, const __nv_bfloat16* __restrict__ Wl,
    float (&d)[12][4], char* smem, uint32_t smem_u32,
    int tid, int g, int q, int warp_m, int warp_n)
{
#pragma unroll
    for (int j = 0; j < 12; j++)
#pragma unroll
        for (int u = 0; u < 4; u++) d[j][u] = 0.f;

    stage_chunk(Wh, Wl, 0, 0, smem_u32, tid);

    const uint32_t* Ahw = reinterpret_cast<const uint32_t*>(smem + SM_AH);
    const uint32_t* Alw = reinterpret_cast<const uint32_t*>(smem + SM_AL);
    const int r0 = warp_m * 16 + g;
    constexpr int S = K / 16;

#pragma unroll 2
    for (int s = 0; s < S; s++) {
        const int b = s & 1;
        if (s + 1 < S) {
            stage_chunk(Wh, Wl, s + 1, b ^ 1, smem_u32, tid);
            asm volatile("cp.async.wait_group 1;");
        } else {
            asm volatile("cp.async.wait_group 0;");
        }
        __syncthreads();

        const int base = r0 * (AST / 2) + s * 8 + q;
        uint32_t ah[4], al[4];
        ah[0] = Ahw[base];
        ah[1] = Ahw[base + 8 * (AST / 2)];
        ah[2] = Ahw[base + 4];
        ah[3] = Ahw[base + 8 * (AST / 2) + 4];
        al[0] = Alw[base];
        al[1] = Alw[base + 8 * (AST / 2)];
        al[2] = Alw[base + 4];
        al[3] = Alw[base + 8 * (AST / 2) + 4];

        // conflict-free LDS.64 B loads: word64 index = n*4 + q
        const uint2* bhp = reinterpret_cast<const uint2*>(smem + SM_W + b * CHUNK_B);
        const uint2* blp = reinterpret_cast<const uint2*>(smem + SM_W + 2 * CHUNK_B + b * CHUNK_B);
#pragma unroll
        for (int j = 0; j < 12; j++) {
            int n = warp_n * 96 + j * 8 + g;
            uint2 bh = bhp[n * 4 + q];
            uint2 bl = blp[n * 4 + q];
            mma_bf16(d[j], ah[0], ah[1], ah[2], ah[3], bh.x, bh.y);
            mma_bf16(d[j], al[0], al[1], al[2], al[3], bh.x, bh.y);
            mma_bf16(d[j], ah[0], ah[1], ah[2], ah[3], bl.x, bl.y);
        }
        __syncthreads();
    }
}

template<bool ACT>
__device__ __forceinline__ void epi_store(
    float (&d)[12][4], const float* __restrict__ bias,
    char* smem, int g, int q, int warp_m, int warp_n)
{
    uint32_t* Ahw = reinterpret_cast<uint32_t*>(smem + SM_AH);
    uint32_t* Alw = reinterpret_cast<uint32_t*>(smem + SM_AL);
    const int r0 = warp_m * 16 + g;
#pragma unroll
    for (int j = 0; j < 12; j++) {
        int c = warp_n * 96 + j * 8 + q * 2;
        float b0 = bias[c], b1 = bias[c + 1];
        float x0 = d[j][0] + b0, x1 = d[j][1] + b1;
        float x2 = d[j][2] + b0, x3 = d[j][3] + b1;
        if (ACT) {
            x0 = x0 / (1.f + __expf(-x0));
            x1 = x1 / (1.f + __expf(-x1));
            x2 = x2 / (1.f + __expf(-x2));
            x3 = x3 / (1.f + __expf(-x3));
        }
        uint32_t hw0, lw0, hw1, lw1;
        split2(x0, x1, hw0, lw0);
        split2(x2, x3, hw1, lw1);
        int w0 = r0 * (AST / 2) + c / 2;
        int w1 = (r0 + 8) * (AST / 2) + c / 2;
        Ahw[w0] = hw0; Alw[w0] = lw0;
        Ahw[w1] = hw1; Alw[w1] = lw1;
    }
    __syncthreads();
}

__global__ __launch_bounds__(NT, 2) void node_kernel(
    const float* __restrict__ b_up, const float* __restrict__ b_lins,
    const float* __restrict__ W_out, float* __restrict__ out, int N)
{
    extern __shared__ char smem[];
    float* sBias = reinterpret_cast<float*>(smem + SM_BIAS);
    float* sRed  = reinterpret_cast<float*>(smem + SM_RED);
    const uint32_t smem_u32 = smem_to_u32(smem);

    const int tid = threadIdx.x;
    const int lane = tid & 31, warp = tid >> 5;
    const int g = lane >> 2, q = lane & 3;
    const int warp_m = warp & 3, warp_n = warp >> 2;
    const int node0 = blockIdx.x * MB;

    for (int t = tid; t < FEA; t += NT) {
        sBias[t]           = b_up[t];
        sBias[FEA + t]     = b_lins[t];
        sBias[2 * FEA + t] = b_lins[FEA + t];
        sBias[3 * FEA + t] = b_lins[2 * FEA + t];
        sBias[4 * FEA + t] = W_out[t];
    }
    // load xn tile [64][256] -> Ah/Al bf16 hi/lo
    {
        uint32_t* Ahw = reinterpret_cast<uint32_t*>(smem + SM_AH);
        uint32_t* Alw = reinterpret_cast<uint32_t*>(smem + SM_AL);
        const int row = tid >> 2, part = tid & 3;
        const int node = node0 + row;
        const bool valid = node < N;
        const float4* src = reinterpret_cast<const float4*>(
            g_xn + (size_t)node * HID + part * 64);
#pragma unroll
        for (int u = 0; u < 16; u++) {
            float4 v = valid ? src[u] : make_float4(0.f, 0.f, 0.f, 0.f);
            uint32_t hw0, lw0, hw1, lw1;
            split2(v.x, v.y, hw0, lw0);
            split2(v.z, v.w, hw1, lw1);
            int w = row * (AST / 2) + part * 32 + u * 2;
            Ahw[w] = hw0;     Alw[w] = lw0;
            Ahw[w + 1] = hw1; Alw[w + 1] = lw1;
        }
    }
    __syncthreads();

    float d[12][4];
    mloop<HID>(g_wh + L0_OFF, g_wl + L0_OFF, d, smem, smem_u32, tid, g, q, warp_m, warp_n);
    epi_store<false>(d, sBias, smem, g, q, warp_m, warp_n);
    mloop<FEA>(g_wh + L_OFF(1), g_wl + L_OFF(1), d, smem, smem_u32, tid, g, q, warp_m, warp_n);
    epi_store<true>(d, sBias + FEA, smem, g, q, warp_m, warp_n);
    mloop<FEA>(g_wh + L_OFF(2), g_wl + L_OFF(2), d, smem, smem_u32, tid, g, q, warp_m, warp_n);
    epi_store<true>(d, sBias + 2 * FEA, smem, g, q, warp_m, warp_n);
    mloop<FEA>(g_wh + L_OFF(3), g_wl + L_OFF(3), d, smem, smem_u32, tid, g, q, warp_m, warp_n);

    // final epilogue: silu + W_out projection fused
    {
        const float* sB3 = sBias + 3 * FEA;
        const float* sWo = sBias + 4 * FEA;
        float s0 = 0.f, s1 = 0.f;
#pragma unroll
        for (int j = 0; j < 12; j++) {
            int c = warp_n * 96 + j * 8 + q * 2;
            float b0 = sB3[c], b1 = sB3[c + 1];
            float w0 = sWo[c], w1 = sWo[c + 1];
            float x0 = d[j][0] + b0, x1 = d[j][1] + b1;
            float x2 = d[j][2] + b0, x3 = d[j][3] + b1;
            x0 = x0 / (1.f + __expf(-x0));
            x1 = x1 / (1.f + __expf(-x1));
            x2 = x2 / (1.f + __expf(-x2));
            x3 = x3 / (1.f + __expf(-x3));
            s0 += x0 * w0 + x1 * w1;
            s1 += x2 * w0 + x3 * w1;
        }
        s0 += __shfl_xor_sync(0xffffffffu, s0, 1);
        s0 += __shfl_xor_sync(0xffffffffu, s0, 2);
        s1 += __shfl_xor_sync(0xffffffffu, s1, 1);
        s1 += __shfl_xor_sync(0xffffffffu, s1, 2);
        const int r0 = warp_m * 16 + g;
        if (q == 0) {
            sRed[warp_n * MB + r0]     = s0;
            sRed[warp_n * MB + r0 + 8] = s1;
        }
        __syncthreads();
        if (tid < MB) {
            int node = node0 + tid;
            if (node < N) out[node] = sRed[tid] + sRed[MB + tid];
        }
    }
}

// ---------------------------------------------------------------------------
// launch
// ---------------------------------------------------------------------------
extern "C" void kernel_launch(void* const* d_in, const int* in_sizes, int n_in,
                              void* d_out, int out_size)
{
    const float* x    = (const float*)d_in[0];
    const float* rbf  = (const float*)d_in[1];
    const void*  idx  = d_in[2];
    const int wo = (n_in >= 10) ? 4 : 3;
    const float* W_rbf  = (const float*)d_in[wo + 0];
    const float* W_up   = (const float*)d_in[wo + 1];
    const float* b_up   = (const float*)d_in[wo + 2];
    const float* W_lins = (const float*)d_in[wo + 3];
    const float* b_lins = (const float*)d_in[wo + 4];
    const float* W_out  = (const float*)d_in[wo + 5];

    const int E = in_sizes[0] / HID;
    const int N = out_size;

    cudaFuncSetAttribute(node_kernel,
                         cudaFuncAttributeMaxDynamicSharedMemorySize, SM_TOT);

    prep_kernel<<<(W_ELEMS + 255) / 256, 256>>>(W_up, W_lins);
    hist_kernel<<<(E + 255) / 256, 256>>>(idx, E);
    scan_kernel<<<1, 1024>>>(N);
    zero_xn_kernel<<<2048, 256>>>(N * HID / 4);
    scatter_kernel<<<(E + 255) / 256, 256>>>(idx, E);
    const int nchunks = (E + 31) / 32;
    gather_kernel<<<(nchunks + 7) / 8, 256>>>(x, rbf, W_rbf, E);
    node_kernel<<<(N + MB - 1) / MB, NT, SM_TOT>>>(
        b_up, b_lins, W_out, (float*)d_out, N);
}

// round 14
// speedup vs baseline: 1.8358x; 1.0478x over previous
#include <cuda_runtime.h>
#include <cuda_bf16.h>
#include <cstdint>

#define HID 256
#define FEA 192
#define NMAX 50000
#define EMAX 800000
#define MB 64           // nodes per block
#define NT 256          // threads per block

typedef unsigned long long ull;

// node kernel smem layout (bytes)
#define AST     264                        // act row stride in halfs (bank-perfect)
#define SM_AH   0
#define SM_AL   (MB * AST * 2)             // 33792
#define SM_W    (2 * MB * AST * 2)         // 67584 (weight chunk buffers)
#define CHUNK_B 6144                       // 192 cols * 32B (dense, conflict-free)
#define SM_BIAS (SM_W + 4 * CHUNK_B)       // 92160
#define SM_RED  (SM_BIAS + 5 * FEA * 4)    // 96000
#define SM_TOT  (SM_RED + 2 * MB * 4)      // 96512 -> 2 CTAs/SM

__device__ float g_xn[(size_t)NMAX * HID];
// CSR sort structures
__device__ int g_cnt[NMAX];
__device__ int g_off[NMAX + 1];
__device__ int g_cur[NMAX];
__device__ int g_sorted[EMAX];
__device__ int g_nid[EMAX];
// pre-split weights, chunked layout: [chunk16][n(192)][16 halfs, frag-order]
#define W_ELEMS (HID * FEA + 3 * FEA * FEA)
__device__ __align__(16) __nv_bfloat16 g_wh[W_ELEMS];
__device__ __align__(16) __nv_bfloat16 g_wl[W_ELEMS];
#define L0_OFF 0
#define L_OFF(l) (HID * FEA + ((l) - 1) * FEA * FEA)

// ---------------------------------------------------------------------------
// helpers
// ---------------------------------------------------------------------------
__device__ __forceinline__ void split1(float v, uint16_t& h, uint16_t& l) {
    __nv_bfloat16 hb = __float2bfloat16(v);
    float r = v - __bfloat162float(hb);
    __nv_bfloat16 lb = __float2bfloat16(r);
    h = __bfloat16_as_ushort(hb);
    l = __bfloat16_as_ushort(lb);
}
__device__ __forceinline__ void split2(float a, float b, uint32_t& hw, uint32_t& lw) {
    uint16_t ha, la, hb, lb;
    split1(a, ha, la);
    split1(b, hb, lb);
    hw = ((uint32_t)hb << 16) | ha;
    lw = ((uint32_t)lb << 16) | la;
}
__device__ __forceinline__ void mma_bf16(float* d,
                                         uint32_t a0, uint32_t a1, uint32_t a2, uint32_t a3,
                                         uint32_t b0, uint32_t b1) {
    asm volatile(
        "mma.sync.aligned.m16n8k16.row.col.f32.bf16.bf16.f32 "
        "{%0,%1,%2,%3}, {%4,%5,%6,%7}, {%8,%9}, {%0,%1,%2,%3};"
        : "+f"(d[0]), "+f"(d[1]), "+f"(d[2]), "+f"(d[3])
        : "r"(a0), "r"(a1), "r"(a2), "r"(a3), "r"(b0), "r"(b1));
}
__device__ __forceinline__ uint32_t smem_to_u32(const void* p) {
    uint32_t a;
    asm("{ .reg .u64 t; cvta.to.shared.u64 t, %1; cvt.u32.u64 %0, t; }"
        : "=r"(a) : "l"(p));
    return a;
}
__device__ __forceinline__ ull fma2(ull a, ull b, ull c) {
    ull d;
    asm("fma.rn.f32x2 %0, %1, %2, %3;" : "=l"(d) : "l"(a), "l"(b), "l"(c));
    return d;
}
__device__ __forceinline__ ull mul2(ull a, ull b) {
    ull d;
    asm("mul.rn.f32x2 %0, %1, %2;" : "=l"(d) : "l"(a), "l"(b));
    return d;
}
__device__ __forceinline__ ull packf2(float lo, float hi) {
    ull d;
    asm("mov.b64 %0, {%1, %2};" : "=l"(d) : "f"(lo), "f"(hi));
    return d;
}
__device__ __forceinline__ void unpackf2(ull v, float& lo, float& hi) {
    asm("mov.b64 {%0, %1}, %2;" : "=f"(lo), "=f"(hi) : "l"(v));
}
// block-local int64-vs-int32 index detection (checks first 512 entries)
__device__ __forceinline__ int block_detect_is64(const void* idx, int E, int tid) {
    __shared__ int bad;
    if (tid == 0) bad = 0;
    __syncthreads();
    int n = E < 512 ? E : 512;
    const unsigned int* w = reinterpret_cast<const unsigned int*>(idx);
    for (int k = tid; k < n; k += NT)
        if (w[2 * k + 1] != 0u) bad = 1;
    __syncthreads();
    return !bad;
}
__device__ __forceinline__ int load_idx(const void* idx, int e, int is64) {
    return is64 ? (int)reinterpret_cast<const long long*>(idx)[e]
                : reinterpret_cast<const int*>(idx)[e];
}

// ---------------------------------------------------------------------------
// prep: split weights to bf16 hi/lo in mma-fragment half order; zero g_cnt
// ---------------------------------------------------------------------------
__global__ void prep_kernel(const float* __restrict__ W_up,
                            const float* __restrict__ W_lins) {
    int t = blockIdx.x * blockDim.x + threadIdx.x;
    if (t < NMAX) g_cnt[t] = 0;
    if (t >= W_ELEMS) return;
    int base, el;
    const float* src;
    if (t < HID * FEA) { base = L0_OFF; el = t; src = W_up; }
    else {
        int t2 = t - HID * FEA;
        int l = t2 / (FEA * FEA);
        base = L_OFF(l + 1);
        el = t2 - l * FEA * FEA;
        src = W_lins + l * FEA * FEA;
    }
    int kf = el / FEA, n = el - kf * FEA;
    uint16_t h, l16;
    split1(src[kf * FEA + n], h, l16);
    int kk = kf & 15;
    int p = (((kk & 7) >> 1) << 2) | (((kk >> 3) & 1) << 1) | (kk & 1);
    int dst = base + (kf >> 4) * (16 * FEA) + n * 16 + p;
    g_wh[dst] = __ushort_as_bfloat16(h);
    g_wl[dst] = __ushort_as_bfloat16(l16);
}

// ---------------------------------------------------------------------------
// sort chain
// ---------------------------------------------------------------------------
__global__ void zero_xn_kernel(int n4) {
    float4* p = reinterpret_cast<float4*>(g_xn);
    const float4 z = make_float4(0.f, 0.f, 0.f, 0.f);
    for (int i = blockIdx.x * blockDim.x + threadIdx.x; i < n4;
         i += gridDim.x * blockDim.x)
        p[i] = z;
}

__global__ __launch_bounds__(NT) void hist_kernel(const void* __restrict__ idx, int E) {
    int is64 = block_detect_is64(idx, E, threadIdx.x);
    int e = blockIdx.x * blockDim.x + threadIdx.x;
    if (e >= E) return;
    atomicAdd(&g_cnt[load_idx(idx, e, is64)], 1);
}

__global__ __launch_bounds__(1024) void scan_kernel(int N) {
    __shared__ int part[1024];
    const int tid = threadIdx.x;
    const int chunk = (N + 1023) / 1024;
    const int base = tid * chunk;
    int s = 0;
    for (int k = 0; k < chunk; k++) {
        int i = base + k;
        if (i < N) s += g_cnt[i];
    }
    part[tid] = s;
    __syncthreads();
    for (int d = 1; d < 1024; d <<= 1) {
        int v = (tid >= d) ? part[tid - d] : 0;
        __syncthreads();
        part[tid] += v;
        __syncthreads();
    }
    int run = part[tid] - s;
    for (int k = 0; k < chunk; k++) {
        int i = base + k;
        if (i < N) {
            g_off[i] = run;
            g_cur[i] = run;
            run += g_cnt[i];
        }
    }
    if (tid == 1023) g_off[N] = part[1023];
}

__global__ __launch_bounds__(NT) void scatter_kernel(const void* __restrict__ idx, int E) {
    int is64 = block_detect_is64(idx, E, threadIdx.x);
    int e = blockIdx.x * blockDim.x + threadIdx.x;
    if (e >= E) return;
    int n = load_idx(idx, e, is64);
    int p = atomicAdd(&g_cur[n], 1);
    g_sorted[p] = e;
    g_nid[p] = n;
}

// ---------------------------------------------------------------------------
// chunk-parallel gather, depth-4 edge pipeline, segmented red.v4 flush
// ---------------------------------------------------------------------------
__global__ __launch_bounds__(256) void gather_kernel(
    const float* __restrict__ x, const float* __restrict__ rbf,
    const float* __restrict__ W_rbf, int E)
{
    const int chunk = (blockIdx.x * blockDim.x + threadIdx.x) >> 5;
    const int lane = threadIdx.x & 31;
    const int c0 = chunk * 32;
    if (c0 >= E) return;
    int m = E - c0;
    if (m > 32) m = 32;

    // W_rbf columns for this lane's 8 channels, packed f32x2
    ull wp[6][4];
#pragma unroll
    for (int r = 0; r < 6; r++) {
        float4 a = *reinterpret_cast<const float4*>(W_rbf + r * HID + lane * 8);
        float4 b = *reinterpret_cast<const float4*>(W_rbf + r * HID + lane * 8 + 4);
        wp[r][0] = packf2(a.x, a.y);
        wp[r][1] = packf2(a.z, a.w);
        wp[r][2] = packf2(b.x, b.y);
        wp[r][3] = packf2(b.z, b.w);
    }

    const int li = lane < m ? lane : m - 1;
    const int eid = g_sorted[c0 + li];
    const int nid = g_nid[c0 + li];

    ull acc[4] = {0ULL, 0ULL, 0ULL, 0ULL};
    int cur = __shfl_sync(0xffffffffu, nid, 0);

    // 4-slot edge ring
    ulonglong2 X0[4], X1[4];
    float2 R0[4], R1[4], R2[4];

    auto loadSlot = [&](int slot, int e) {
        const ulonglong2* xp =
            reinterpret_cast<const ulonglong2*>(x + (size_t)e * HID + lane * 8);
        X0[slot] = xp[0];
        X1[slot] = xp[1];
        const float2* rp = reinterpret_cast<const float2*>(rbf + (size_t)e * 6);
        R0[slot] = rp[0];
        R1[slot] = rp[1];
        R2[slot] = rp[2];
    };
    auto computeSlot = [&](int slot) {
        ull q0 = packf2(R0[slot].x, R0[slot].x), q1 = packf2(R0[slot].y, R0[slot].y);
        ull q2 = packf2(R1[slot].x, R1[slot].x), q3 = packf2(R1[slot].y, R1[slot].y);
        ull q4 = packf2(R2[slot].x, R2[slot].x), q5 = packf2(R2[slot].y, R2[slot].y);
        ull xv[4] = {X0[slot].x, X0[slot].y, X1[slot].x, X1[slot].y};
#pragma unroll
        for (int p = 0; p < 4; p++) {
            ull g = mul2(q0, wp[0][p]);
            g = fma2(q1, wp[1][p], g);
            g = fma2(q2, wp[2][p], g);
            g = fma2(q3, wp[3][p], g);
            g = fma2(q4, wp[4][p], g);
            g = fma2(q5, wp[5][p], g);
            acc[p] = fma2(g, xv[p], acc[p]);
        }
    };
    auto flush = [&](int node) {
        float f0, f1, f2, f3, f4, f5, f6, f7;
        unpackf2(acc[0], f0, f1);
        unpackf2(acc[1], f2, f3);
        unpackf2(acc[2], f4, f5);
        unpackf2(acc[3], f6, f7);
        float* p = g_xn + (size_t)node * HID + lane * 8;
        asm volatile("red.global.add.v4.f32 [%0], {%1, %2, %3, %4};"
                     :: "l"(p), "f"(f0), "f"(f1), "f"(f2), "f"(f3) : "memory");
        asm volatile("red.global.add.v4.f32 [%0], {%1, %2, %3, %4};"
                     :: "l"(p + 4), "f"(f4), "f"(f5), "f"(f6), "f"(f7) : "memory");
        acc[0] = acc[1] = acc[2] = acc[3] = 0ULL;
    };

    if (m == 32) {
        // fast path: constant trip count, depth-4 pipeline, slot idx constant
        // per unrolled copy
#pragma unroll
        for (int p = 0; p < 4; p++)
            loadSlot(p, __shfl_sync(0xffffffffu, eid, p));
#pragma unroll 4
        for (int j = 0; j < 32; j++) {
            int nj = __shfl_sync(0xffffffffu, nid, j);
            if (nj != cur) { flush(cur); cur = nj; }
            computeSlot(j & 3);
            if (j + 4 < 32)
                loadSlot(j & 3, __shfl_sync(0xffffffffu, eid, j + 4));
        }
    } else {
        // tail chunk (at most one per grid): simple depth-1
        for (int j = 0; j < m; j++) {
            int nj = __shfl_sync(0xffffffffu, nid, j);
            if (nj != cur) { flush(cur); cur = nj; }
            loadSlot(0, __shfl_sync(0xffffffffu, eid, j));
            computeSlot(0);
        }
    }
    flush(cur);
}

// ---------------------------------------------------------------------------
// node MLP: mma.sync bf16 3-term split; conflict-free vectorized B loads
// ---------------------------------------------------------------------------
__device__ __forceinline__ void stage_chunk(
    const __nv_bfloat16* __restrict__ Wh, const __nv_bfloat16* __restrict__ Wl,
    int s, int buf, uint32_t smem_u32, int tid)
{
    const char* srcH = reinterpret_cast<const char*>(Wh + s * 16 * FEA);
    const char* srcL = reinterpret_cast<const char*>(Wl + s * 16 * FEA);
#pragma unroll
    for (int it = 0; it < 3; it++) {
        int t = tid + it * NT;                // 0..767
        int term = t >= 384;
        int u = term ? t - 384 : t;           // 0..383
        int n = u >> 1, seg = u & 1;
        const char* src = (term ? srcL : srcH) + n * 32 + seg * 16;
        uint32_t dst = smem_u32 + SM_W + term * (2 * CHUNK_B) + buf * CHUNK_B
                     + n * 32 + seg * 16;
        asm volatile("cp.async.cg.shared.global [%0], [%1], 16;"
                     :: "r"(dst), "l"(src));
    }
    asm volatile("cp.async.commit_group;");
}

template<int K>
__device__ __forceinline__ void mloop(
    const __nv_bfloat16* __restrict__ Wh, const __nv_bfloat16* __restrict__ Wl,
    float (&d)[12][4], char* smem, uint32_t smem_u32,
    int tid, int g, int q, int warp_m, int warp_n)
{
#pragma unroll
    for (int j = 0; j < 12; j++)
#pragma unroll
        for (int u = 0; u < 4; u++) d[j][u] = 0.f;

    stage_chunk(Wh, Wl, 0, 0, smem_u32, tid);

    const uint32_t* Ahw = reinterpret_cast<const uint32_t*>(smem + SM_AH);
    const uint32_t* Alw = reinterpret_cast<const uint32_t*>(smem + SM_AL);
    const int r0 = warp_m * 16 + g;
    constexpr int S = K / 16;

#pragma unroll 2
    for (int s = 0; s < S; s++) {
        const int b = s & 1;
        if (s + 1 < S) {
            stage_chunk(Wh, Wl, s + 1, b ^ 1, smem_u32, tid);
            asm volatile("cp.async.wait_group 1;");
        } else {
            asm volatile("cp.async.wait_group 0;");
        }
        __syncthreads();

        const int base = r0 * (AST / 2) + s * 8 + q;
        uint32_t ah[4], al[4];
        ah[0] = Ahw[base];
        ah[1] = Ahw[base + 8 * (AST / 2)];
        ah[2] = Ahw[base + 4];
        ah[3] = Ahw[base + 8 * (AST / 2) + 4];
        al[0] = Alw[base];
        al[1] = Alw[base + 8 * (AST / 2)];
        al[2] = Alw[base + 4];
        al[3] = Alw[base + 8 * (AST / 2) + 4];

        // conflict-free LDS.64 B loads: word64 index = n*4 + q
        const uint2* bhp = reinterpret_cast<const uint2*>(smem + SM_W + b * CHUNK_B);
        const uint2* blp = reinterpret_cast<const uint2*>(smem + SM_W + 2 * CHUNK_B + b * CHUNK_B);
#pragma unroll
        for (int j = 0; j < 12; j++) {
            int n = warp_n * 96 + j * 8 + g;
            uint2 bh = bhp[n * 4 + q];
            uint2 bl = blp[n * 4 + q];
            mma_bf16(d[j], ah[0], ah[1], ah[2], ah[3], bh.x, bh.y);
            mma_bf16(d[j], al[0], al[1], al[2], al[3], bh.x, bh.y);
            mma_bf16(d[j], ah[0], ah[1], ah[2], ah[3], bl.x, bl.y);
        }
        __syncthreads();
    }
}

template<bool ACT>
__device__ __forceinline__ void epi_store(
    float (&d)[12][4], const float* __restrict__ bias,
    char* smem, int g, int q, int warp_m, int warp_n)
{
    uint32_t* Ahw = reinterpret_cast<uint32_t*>(smem + SM_AH);
    uint32_t* Alw = reinterpret_cast<uint32_t*>(smem + SM_AL);
    const int r0 = warp_m * 16 + g;
#pragma unroll
    for (int j = 0; j < 12; j++) {
        int c = warp_n * 96 + j * 8 + q * 2;
        float b0 = bias[c], b1 = bias[c + 1];
        float x0 = d[j][0] + b0, x1 = d[j][1] + b1;
        float x2 = d[j][2] + b0, x3 = d[j][3] + b1;
        if (ACT) {
            x0 = x0 / (1.f + __expf(-x0));
            x1 = x1 / (1.f + __expf(-x1));
            x2 = x2 / (1.f + __expf(-x2));
            x3 = x3 / (1.f + __expf(-x3));
        }
        uint32_t hw0, lw0, hw1, lw1;
        split2(x0, x1, hw0, lw0);
        split2(x2, x3, hw1, lw1);
        int w0 = r0 * (AST / 2) + c / 2;
        int w1 = (r0 + 8) * (AST / 2) + c / 2;
        Ahw[w0] = hw0; Alw[w0] = lw0;
        Ahw[w1] = hw1; Alw[w1] = lw1;
    }
    __syncthreads();
}

__global__ __launch_bounds__(NT, 2) void node_kernel(
    const float* __restrict__ b_up, const float* __restrict__ b_lins,
    const float* __restrict__ W_out, float* __restrict__ out, int N)
{
    extern __shared__ char smem[];
    float* sBias = reinterpret_cast<float*>(smem + SM_BIAS);
    float* sRed  = reinterpret_cast<float*>(smem + SM_RED);
    const uint32_t smem_u32 = smem_to_u32(smem);

    const int tid = threadIdx.x;
    const int lane = tid & 31, warp = tid >> 5;
    const int g = lane >> 2, q = lane & 3;
    const int warp_m = warp & 3, warp_n = warp >> 2;
    const int node0 = blockIdx.x * MB;

    for (int t = tid; t < FEA; t += NT) {
        sBias[t]           = b_up[t];
        sBias[FEA + t]     = b_lins[t];
        sBias[2 * FEA + t] = b_lins[FEA + t];
        sBias[3 * FEA + t] = b_lins[2 * FEA + t];
        sBias[4 * FEA + t] = W_out[t];
    }
    // load xn tile [64][256] -> Ah/Al bf16 hi/lo
    {
        uint32_t* Ahw = reinterpret_cast<uint32_t*>(smem + SM_AH);
        uint32_t* Alw = reinterpret_cast<uint32_t*>(smem + SM_AL);
        const int row = tid >> 2, part = tid & 3;
        const int node = node0 + row;
        const bool valid = node < N;
        const float4* src = reinterpret_cast<const float4*>(
            g_xn + (size_t)node * HID + part * 64);
#pragma unroll
        for (int u = 0; u < 16; u++) {
            float4 v = valid ? src[u] : make_float4(0.f, 0.f, 0.f, 0.f);
            uint32_t hw0, lw0, hw1, lw1;
            split2(v.x, v.y, hw0, lw0);
            split2(v.z, v.w, hw1, lw1);
            int w = row * (AST / 2) + part * 32 + u * 2;
            Ahw[w] = hw0;     Alw[w] = lw0;
            Ahw[w + 1] = hw1; Alw[w + 1] = lw1;
        }
    }
    __syncthreads();

    float d[12][4];
    mloop<HID>(g_wh + L0_OFF, g_wl + L0_OFF, d, smem, smem_u32, tid, g, q, warp_m, warp_n);
    epi_store<false>(d, sBias, smem, g, q, warp_m, warp_n);
    mloop<FEA>(g_wh + L_OFF(1), g_wl + L_OFF(1), d, smem, smem_u32, tid, g, q, warp_m, warp_n);
    epi_store<true>(d, sBias + FEA, smem, g, q, warp_m, warp_n);
    mloop<FEA>(g_wh + L_OFF(2), g_wl + L_OFF(2), d, smem, smem_u32, tid, g, q, warp_m, warp_n);
    epi_store<true>(d, sBias + 2 * FEA, smem, g, q, warp_m, warp_n);
    mloop<FEA>(g_wh + L_OFF(3), g_wl + L_OFF(3), d, smem, smem_u32, tid, g, q, warp_m, warp_n);

    // final epilogue: silu + W_out projection fused
    {
        const float* sB3 = sBias + 3 * FEA;
        const float* sWo = sBias + 4 * FEA;
        float s0 = 0.f, s1 = 0.f;
#pragma unroll
        for (int j = 0; j < 12; j++) {
            int c = warp_n * 96 + j * 8 + q * 2;
            float b0 = sB3[c], b1 = sB3[c + 1];
            float w0 = sWo[c], w1 = sWo[c + 1];
            float x0 = d[j][0] + b0, x1 = d[j][1] + b1;
            float x2 = d[j][2] + b0, x3 = d[j][3] + b1;
            x0 = x0 / (1.f + __expf(-x0));
            x1 = x1 / (1.f + __expf(-x1));
            x2 = x2 / (1.f + __expf(-x2));
            x3 = x3 / (1.f + __expf(-x3));
            s0 += x0 * w0 + x1 * w1;
            s1 += x2 * w0 + x3 * w1;
        }
        s0 += __shfl_xor_sync(0xffffffffu, s0, 1);
        s0 += __shfl_xor_sync(0xffffffffu, s0, 2);
        s1 += __shfl_xor_sync(0xffffffffu, s1, 1);
        s1 += __shfl_xor_sync(0xffffffffu, s1, 2);
        const int r0 = warp_m * 16 + g;
        if (q == 0) {
            sRed[warp_n * MB + r0]     = s0;
            sRed[warp_n * MB + r0 + 8] = s1;
        }
        __syncthreads();
        if (tid < MB) {
            int node = node0 + tid;
            if (node < N) out[node] = sRed[tid] + sRed[MB + tid];
        }
    }
}

// ---------------------------------------------------------------------------
// launch
// ---------------------------------------------------------------------------
extern "C" void kernel_launch(void* const* d_in, const int* in_sizes, int n_in,
                              void* d_out, int out_size)
{
    const float* x    = (const float*)d_in[0];
    const float* rbf  = (const float*)d_in[1];
    const void*  idx  = d_in[2];
    const int wo = (n_in >= 10) ? 4 : 3;
    const float* W_rbf  = (const float*)d_in[wo + 0];
    const float* W_up   = (const float*)d_in[wo + 1];
    const float* b_up   = (const float*)d_in[wo + 2];
    const float* W_lins = (const float*)d_in[wo + 3];
    const float* b_lins = (const float*)d_in[wo + 4];
    const float* W_out  = (const float*)d_in[wo + 5];

    const int E = in_sizes[0] / HID;
    const int N = out_size;

    cudaFuncSetAttribute(node_kernel,
                         cudaFuncAttributeMaxDynamicSharedMemorySize, SM_TOT);

    prep_kernel<<<(W_ELEMS + 255) / 256, 256>>>(W_up, W_lins);
    hist_kernel<<<(E + 255) / 256, 256>>>(idx, E);
    scan_kernel<<<1, 1024>>>(N);
    zero_xn_kernel<<<2048, 256>>>(N * HID / 4);
    scatter_kernel<<<(E + 255) / 256, 256>>>(idx, E);
    const int nchunks = (E + 31) / 32;
    gather_kernel<<<(nchunks + 7) / 8, 256>>>(x, rbf, W_rbf, E);
    node_kernel<<<(N + MB - 1) / MB, NT, SM_TOT>>>(
        b_up, b_lins, W_out, (float*)d_out, N);
}